// round 1
// baseline (speedup 1.0000x reference)
#include <cuda_runtime.h>
#include <math.h>

#define N_TOK   16384
#define E_DIM   512
#define B_GRP   32
#define L_SEQ   512
#define H_HEADS 8
#define DH      64

// Scratch (no allocation allowed -> __device__ globals)
__device__ float g_qkv[N_TOK * 3 * E_DIM];   // [N, 3E]  (Q | K | V)
__device__ float g_ctx[N_TOK * E_DIM];       // [N, E]
__device__ float g_attn[N_TOK * E_DIM];      // [N, E]

// ---------------------------------------------------------------------------
// SGEMM (NT): C[M,Nn] = A[M,K] @ W[Nn,K]^T + bias[Nn]
// 128x128 block, BK=16, 256 threads, 8x8 per-thread microtile.
// ---------------------------------------------------------------------------
#define BM 128
#define BN 128
#define BK 16
#define PAD_BM 132

__global__ __launch_bounds__(256, 2) void sgemm_nt_bias(
    const float* __restrict__ A, const float* __restrict__ W,
    const float* __restrict__ bias, float* __restrict__ C,
    int M, int Nn, int K)
{
    __shared__ float As[BK][PAD_BM];
    __shared__ float Bs[BK][PAD_BM];

    const int tid  = threadIdx.x;
    const int brow = blockIdx.y * BM;
    const int bcol = blockIdx.x * BN;
    const int la_row = tid >> 2;          // 0..63
    const int la_col = (tid & 3) << 2;    // 0,4,8,12
    const int ty = tid >> 4;              // 0..15
    const int tx = tid & 15;              // 0..15

    float acc[8][8];
#pragma unroll
    for (int i = 0; i < 8; i++)
#pragma unroll
        for (int j = 0; j < 8; j++) acc[i][j] = 0.f;

    const float* Ab = A + (size_t)brow * K;
    const float* Wb = W + (size_t)bcol * K;

    for (int k0 = 0; k0 < K; k0 += BK) {
#pragma unroll
        for (int r = 0; r < 2; r++) {
            const int row = la_row + r * 64;
            float4 va = *(const float4*)(Ab + (size_t)row * K + k0 + la_col);
            As[la_col + 0][row] = va.x;
            As[la_col + 1][row] = va.y;
            As[la_col + 2][row] = va.z;
            As[la_col + 3][row] = va.w;
            float4 vb = *(const float4*)(Wb + (size_t)row * K + k0 + la_col);
            Bs[la_col + 0][row] = vb.x;
            Bs[la_col + 1][row] = vb.y;
            Bs[la_col + 2][row] = vb.z;
            Bs[la_col + 3][row] = vb.w;
        }
        __syncthreads();
#pragma unroll
        for (int kk = 0; kk < BK; kk++) {
            float a[8], b[8];
            *(float4*)&a[0] = *(const float4*)&As[kk][ty * 8];
            *(float4*)&a[4] = *(const float4*)&As[kk][ty * 8 + 4];
            *(float4*)&b[0] = *(const float4*)&Bs[kk][tx * 8];
            *(float4*)&b[4] = *(const float4*)&Bs[kk][tx * 8 + 4];
#pragma unroll
            for (int i = 0; i < 8; i++)
#pragma unroll
                for (int j = 0; j < 8; j++)
                    acc[i][j] += a[i] * b[j];
        }
        __syncthreads();
    }

    float bv[8];
#pragma unroll
    for (int j = 0; j < 8; j++) bv[j] = bias[bcol + tx * 8 + j];

#pragma unroll
    for (int i = 0; i < 8; i++) {
        const int row = brow + ty * 8 + i;
        float4 o0 = make_float4(acc[i][0] + bv[0], acc[i][1] + bv[1],
                                acc[i][2] + bv[2], acc[i][3] + bv[3]);
        float4 o1 = make_float4(acc[i][4] + bv[4], acc[i][5] + bv[5],
                                acc[i][6] + bv[6], acc[i][7] + bv[7]);
        *(float4*)(C + (size_t)row * Nn + bcol + tx * 8)     = o0;
        *(float4*)(C + (size_t)row * Nn + bcol + tx * 8 + 4) = o1;
    }
}

// ---------------------------------------------------------------------------
// Fused flash attention for one (b, h, 64-row q-tile) per CTA.
// Full mask-free softmax over L=512 keys (all groups full -> mask == 0).
// 256 threads = 16x16; each thread owns a 4(q) x 4(k or d) fragment.
// ---------------------------------------------------------------------------
__global__ __launch_bounds__(256, 2) void attn_kernel(
    const float* __restrict__ qkv, float* __restrict__ ctx)
{
    __shared__ float sQ[64][68];   // [d][q]  (transposed, padded)
    __shared__ float sK[64][68];   // [d][k]  (transposed, padded)
    __shared__ float sV[64][64];   // [k][d]
    __shared__ float sP[64][64];   // [q][k]

    const int tid = threadIdx.x;
    const int qt  = blockIdx.x & 7;       // q tile 0..7
    const int bh  = blockIdx.x >> 3;      // 0..255
    const int h   = bh & 7;
    const int b   = bh >> 3;

    const int ty = tid >> 4;   // 0..15 -> q rows 4*ty..4*ty+3
    const int tx = tid & 15;   // 0..15 -> cols  4*tx..4*tx+3

    const size_t stride = 3 * E_DIM;
    const float* Qg = qkv + (size_t)(b * L_SEQ + qt * 64) * stride + h * DH;
    const float* Kg = qkv + (size_t)(b * L_SEQ) * stride + E_DIM + h * DH;
    const float* Vg = qkv + (size_t)(b * L_SEQ) * stride + 2 * E_DIM + h * DH;

    // ---- load Q tile (transposed into sQ[d][q]) ----
    {
        const int r0 = tid >> 4;
        const int d4 = (tid & 15) << 2;
#pragma unroll
        for (int p = 0; p < 4; p++) {
            const int q = r0 + p * 16;
            float4 v = *(const float4*)(Qg + (size_t)q * stride + d4);
            sQ[d4 + 0][q] = v.x;
            sQ[d4 + 1][q] = v.y;
            sQ[d4 + 2][q] = v.z;
            sQ[d4 + 3][q] = v.w;
        }
    }

    float O[4][4];
    float m_r[4], l_r[4];
#pragma unroll
    for (int i = 0; i < 4; i++) {
        m_r[i] = -INFINITY;
        l_r[i] = 0.f;
#pragma unroll
        for (int j = 0; j < 4; j++) O[i][j] = 0.f;
    }

    for (int kt = 0; kt < 8; kt++) {
        // ---- load K tile (transposed) and V tile ----
        {
            const int r0 = tid >> 4;
            const int d4 = (tid & 15) << 2;
#pragma unroll
            for (int p = 0; p < 4; p++) {
                const int kk = r0 + p * 16;
                float4 vk = *(const float4*)(Kg + (size_t)(kt * 64 + kk) * stride + d4);
                sK[d4 + 0][kk] = vk.x;
                sK[d4 + 1][kk] = vk.y;
                sK[d4 + 2][kk] = vk.z;
                sK[d4 + 3][kk] = vk.w;
                float4 vv = *(const float4*)(Vg + (size_t)(kt * 64 + kk) * stride + d4);
                *(float4*)&sV[kk][d4] = vv;
            }
        }
        __syncthreads();

        // ---- S = Q @ K^T (this tile) ----
        float S[4][4];
#pragma unroll
        for (int i = 0; i < 4; i++)
#pragma unroll
            for (int j = 0; j < 4; j++) S[i][j] = 0.f;

#pragma unroll 8
        for (int d = 0; d < 64; d++) {
            float aq[4], bk[4];
            *(float4*)aq = *(const float4*)&sQ[d][ty * 4];
            *(float4*)bk = *(const float4*)&sK[d][tx * 4];
#pragma unroll
            for (int i = 0; i < 4; i++)
#pragma unroll
                for (int j = 0; j < 4; j++)
                    S[i][j] += aq[i] * bk[j];
        }

        // ---- online softmax (rows reduced over 16 tx-lanes, width-16 shuffles) ----
#pragma unroll
        for (int i = 0; i < 4; i++) {
#pragma unroll
            for (int j = 0; j < 4; j++) S[i][j] *= 0.125f;   // 1/sqrt(64)

            float rm = fmaxf(fmaxf(S[i][0], S[i][1]), fmaxf(S[i][2], S[i][3]));
#pragma unroll
            for (int msk = 1; msk < 16; msk <<= 1)
                rm = fmaxf(rm, __shfl_xor_sync(0xffffffffu, rm, msk));

            const float mn    = fmaxf(m_r[i], rm);
            const float alpha = __expf(m_r[i] - mn);
            m_r[i] = mn;

            float rs = 0.f;
#pragma unroll
            for (int j = 0; j < 4; j++) {
                S[i][j] = __expf(S[i][j] - mn);
                rs += S[i][j];
            }
#pragma unroll
            for (int msk = 1; msk < 16; msk <<= 1)
                rs += __shfl_xor_sync(0xffffffffu, rs, msk);

            l_r[i] = l_r[i] * alpha + rs;
#pragma unroll
            for (int j = 0; j < 4; j++) O[i][j] *= alpha;
        }

        // ---- write P to smem ----
#pragma unroll
        for (int i = 0; i < 4; i++)
#pragma unroll
            for (int j = 0; j < 4; j++)
                sP[ty * 4 + i][tx * 4 + j] = S[i][j];
        __syncthreads();

        // ---- O += P @ V ----
#pragma unroll 8
        for (int kk = 0; kk < 64; kk++) {
            float pf[4], vf[4];
#pragma unroll
            for (int i = 0; i < 4; i++) pf[i] = sP[ty * 4 + i][kk];
            *(float4*)vf = *(const float4*)&sV[kk][tx * 4];
#pragma unroll
            for (int i = 0; i < 4; i++)
#pragma unroll
                for (int j = 0; j < 4; j++)
                    O[i][j] += pf[i] * vf[j];
        }
        __syncthreads();
    }

    // ---- normalize + store ctx ----
#pragma unroll
    for (int i = 0; i < 4; i++) {
        const float inv = 1.f / l_r[i];
        const int n = b * L_SEQ + qt * 64 + ty * 4 + i;
        float4 o = make_float4(O[i][0] * inv, O[i][1] * inv,
                               O[i][2] * inv, O[i][3] * inv);
        *(float4*)(ctx + (size_t)n * E_DIM + h * DH + tx * 4) = o;
    }
}

// ---------------------------------------------------------------------------
// Max over sequence: out[b][e] = max_l attn[(b*L+l)*E + e]
// ---------------------------------------------------------------------------
__global__ void maxpool_kernel(const float* __restrict__ attn, float* __restrict__ out)
{
    const int b = blockIdx.x;
    const int e = threadIdx.x;
    const float* p = attn + (size_t)b * L_SEQ * E_DIM + e;
    float m = -INFINITY;
#pragma unroll 8
    for (int l = 0; l < L_SEQ; l++)
        m = fmaxf(m, p[(size_t)l * E_DIM]);
    out[b * E_DIM + e] = m;
}

// ---------------------------------------------------------------------------
extern "C" void kernel_launch(void* const* d_in, const int* in_sizes, int n_in,
                              void* d_out, int out_size)
{
    const float* emb   = (const float*)d_in[0];
    // d_in[1] = batch (int32) — groups are equal-size & sorted, not needed
    const float* w_in  = (const float*)d_in[2];
    const float* b_in  = (const float*)d_in[3];
    const float* w_out = (const float*)d_in[4];
    const float* b_out = (const float*)d_in[5];
    float* out = (float*)d_out;

    float *qkv_p, *ctx_p, *attn_p;
    cudaGetSymbolAddress((void**)&qkv_p,  g_qkv);
    cudaGetSymbolAddress((void**)&ctx_p,  g_ctx);
    cudaGetSymbolAddress((void**)&attn_p, g_attn);

    // 1) QKV projection: [16384,512] @ [512,1536]^T + b
    dim3 g1((3 * E_DIM) / BN, N_TOK / BM);
    sgemm_nt_bias<<<g1, 256>>>(emb, w_in, b_in, qkv_p, N_TOK, 3 * E_DIM, E_DIM);

    // 2) fused attention: 32 groups x 8 heads x 8 q-tiles
    attn_kernel<<<B_GRP * H_HEADS * 8, 256>>>(qkv_p, ctx_p);

    // 3) out projection: [16384,512] @ [512,512]^T + b
    dim3 g3(E_DIM / BN, N_TOK / BM);
    sgemm_nt_bias<<<g3, 256>>>(ctx_p, w_out, b_out, attn_p, N_TOK, E_DIM, E_DIM);

    // 4) max over sequence -> [32, 512]
    maxpool_kernel<<<B_GRP, E_DIM>>>(attn_p, out);
}

// round 3
// speedup vs baseline: 1.6843x; 1.6843x over previous
#include <cuda_runtime.h>
#include <math.h>
#include <stdint.h>

#define N_TOK   16384
#define E_DIM   512
#define B_GRP   32
#define L_SEQ   512
#define H_HEADS 8
#define DH      64

// Scratch (no allocation allowed -> __device__ globals)
__device__ float g_qkv[N_TOK * 3 * E_DIM];      // [N, 3E]  (Q | K | V)
__device__ float g_ctx[N_TOK * E_DIM];          // [N, E]
__device__ float g_attn[N_TOK * E_DIM];         // [N, E]
__device__ float g_part[B_GRP * 8 * E_DIM];     // maxpool partials

// ---------------------------------------------------------------------------
// TF32 tensor-core helpers
// ---------------------------------------------------------------------------
__device__ __forceinline__ uint32_t f2tf32(float x) {
    uint32_t r;
    asm("cvt.rna.tf32.f32 %0, %1;" : "=r"(r) : "f"(x));
    return r;
}

__device__ __forceinline__ void mma_tf32(float* d, const uint32_t* a,
                                         const uint32_t* b, const float* c) {
    asm volatile(
        "mma.sync.aligned.m16n8k8.row.col.f32.tf32.tf32.f32 "
        "{%0,%1,%2,%3}, {%4,%5,%6,%7}, {%8,%9}, {%10,%11,%12,%13};\n"
        : "=f"(d[0]), "=f"(d[1]), "=f"(d[2]), "=f"(d[3])
        : "r"(a[0]), "r"(a[1]), "r"(a[2]), "r"(a[3]),
          "r"(b[0]), "r"(b[1]),
          "f"(c[0]), "f"(c[1]), "f"(c[2]), "f"(c[3]));
}

// ---------------------------------------------------------------------------
// TF32 SGEMM (NT): C[M,Nn] = A[M,K] @ W[Nn,K]^T + bias
// 128x128 CTA tile, BK=32, 256 threads (8 warps, 2x4), warp tile 64x32.
// ---------------------------------------------------------------------------
#define TBM 128
#define TBN 128
#define TBK 32
#define TPITCH (TBK + 4)   // 36 floats -> conflict-free frag loads

__global__ __launch_bounds__(256, 2) void sgemm_tf32_bias(
    const float* __restrict__ A, const float* __restrict__ W,
    const float* __restrict__ bias, float* __restrict__ C,
    int M, int Nn, int K)
{
    __shared__ __align__(16) float As[TBM][TPITCH];
    __shared__ __align__(16) float Bs[TBN][TPITCH];

    const int tid  = threadIdx.x;
    const int warp = tid >> 5;
    const int lane = tid & 31;
    const int wm   = warp >> 2;     // 0..1 : 64-row band
    const int wn   = warp & 3;      // 0..3 : 32-col band
    const int g    = lane >> 2;     // 0..7
    const int q    = lane & 3;      // 0..3

    const int brow = blockIdx.y * TBM;
    const int bcol = blockIdx.x * TBN;

    float acc[4][4][4];
#pragma unroll
    for (int mt = 0; mt < 4; mt++)
#pragma unroll
        for (int nt = 0; nt < 4; nt++)
#pragma unroll
            for (int i = 0; i < 4; i++) acc[mt][nt][i] = 0.f;

    const float* Ab = A + (size_t)brow * K;
    const float* Wb = W + (size_t)bcol * K;

    const int lrow = tid >> 3;        // 0..31
    const int lcol = (tid & 7) << 2;  // 0..28 step 4

    for (int k0 = 0; k0 < K; k0 += TBK) {
        // ---- stage tiles (convert to tf32 with round-to-nearest) ----
#pragma unroll
        for (int r = 0; r < 4; r++) {
            const int row = lrow + r * 32;
            float4 va = *(const float4*)(Ab + (size_t)row * K + k0 + lcol);
            float4 ta;
            ta.x = __uint_as_float(f2tf32(va.x));
            ta.y = __uint_as_float(f2tf32(va.y));
            ta.z = __uint_as_float(f2tf32(va.z));
            ta.w = __uint_as_float(f2tf32(va.w));
            *(float4*)&As[row][lcol] = ta;

            float4 vb = *(const float4*)(Wb + (size_t)row * K + k0 + lcol);
            float4 tb;
            tb.x = __uint_as_float(f2tf32(vb.x));
            tb.y = __uint_as_float(f2tf32(vb.y));
            tb.z = __uint_as_float(f2tf32(vb.z));
            tb.w = __uint_as_float(f2tf32(vb.w));
            *(float4*)&Bs[row][lcol] = tb;
        }
        __syncthreads();

        // ---- 4 k-steps of 8 ----
#pragma unroll
        for (int ks = 0; ks < 4; ks++) {
            const int k = ks * 8;
            uint32_t af[4][4];
            uint32_t bf[4][2];
#pragma unroll
            for (int mt = 0; mt < 4; mt++) {
                const int r0 = wm * 64 + mt * 16 + g;
                af[mt][0] = __float_as_uint(As[r0][k + q]);
                af[mt][1] = __float_as_uint(As[r0 + 8][k + q]);
                af[mt][2] = __float_as_uint(As[r0][k + 4 + q]);
                af[mt][3] = __float_as_uint(As[r0 + 8][k + 4 + q]);
            }
#pragma unroll
            for (int nt = 0; nt < 4; nt++) {
                const int c0 = wn * 32 + nt * 8 + g;
                bf[nt][0] = __float_as_uint(Bs[c0][k + q]);
                bf[nt][1] = __float_as_uint(Bs[c0][k + 4 + q]);
            }
#pragma unroll
            for (int mt = 0; mt < 4; mt++)
#pragma unroll
                for (int nt = 0; nt < 4; nt++)
                    mma_tf32(acc[mt][nt], af[mt], bf[nt], acc[mt][nt]);
        }
        __syncthreads();
    }

    // ---- epilogue: bias + store (float2 per half-tile) ----
#pragma unroll
    for (int nt = 0; nt < 4; nt++) {
        const int col = bcol + wn * 32 + nt * 8 + 2 * q;
        const float b0 = bias[col];
        const float b1 = bias[col + 1];
#pragma unroll
        for (int mt = 0; mt < 4; mt++) {
            const int r0 = brow + wm * 64 + mt * 16 + g;
            float2 v0 = make_float2(acc[mt][nt][0] + b0, acc[mt][nt][1] + b1);
            float2 v1 = make_float2(acc[mt][nt][2] + b0, acc[mt][nt][3] + b1);
            *(float2*)(C + (size_t)r0 * Nn + col)       = v0;
            *(float2*)(C + (size_t)(r0 + 8) * Nn + col) = v1;
        }
    }
}

// ---------------------------------------------------------------------------
// Fused flash attention (SIMT fp32, unchanged from R1 — tensorize next round)
// ---------------------------------------------------------------------------
__global__ __launch_bounds__(256, 2) void attn_kernel(
    const float* __restrict__ qkv, float* __restrict__ ctx)
{
    __shared__ float sQ[64][68];   // [d][q]
    __shared__ float sK[64][68];   // [d][k]
    __shared__ float sV[64][64];   // [k][d]
    __shared__ float sP[64][64];   // [q][k]

    const int tid = threadIdx.x;
    const int qt  = blockIdx.x & 7;
    const int bh  = blockIdx.x >> 3;
    const int h   = bh & 7;
    const int b   = bh >> 3;

    const int ty = tid >> 4;
    const int tx = tid & 15;

    const size_t stride = 3 * E_DIM;
    const float* Qg = qkv + (size_t)(b * L_SEQ + qt * 64) * stride + h * DH;
    const float* Kg = qkv + (size_t)(b * L_SEQ) * stride + E_DIM + h * DH;
    const float* Vg = qkv + (size_t)(b * L_SEQ) * stride + 2 * E_DIM + h * DH;

    {
        const int r0 = tid >> 4;
        const int d4 = (tid & 15) << 2;
#pragma unroll
        for (int p = 0; p < 4; p++) {
            const int qq = r0 + p * 16;
            float4 v = *(const float4*)(Qg + (size_t)qq * stride + d4);
            sQ[d4 + 0][qq] = v.x;
            sQ[d4 + 1][qq] = v.y;
            sQ[d4 + 2][qq] = v.z;
            sQ[d4 + 3][qq] = v.w;
        }
    }

    float O[4][4];
    float m_r[4], l_r[4];
#pragma unroll
    for (int i = 0; i < 4; i++) {
        m_r[i] = -INFINITY;
        l_r[i] = 0.f;
#pragma unroll
        for (int j = 0; j < 4; j++) O[i][j] = 0.f;
    }

    for (int kt = 0; kt < 8; kt++) {
        {
            const int r0 = tid >> 4;
            const int d4 = (tid & 15) << 2;
#pragma unroll
            for (int p = 0; p < 4; p++) {
                const int kk = r0 + p * 16;
                float4 vk = *(const float4*)(Kg + (size_t)(kt * 64 + kk) * stride + d4);
                sK[d4 + 0][kk] = vk.x;
                sK[d4 + 1][kk] = vk.y;
                sK[d4 + 2][kk] = vk.z;
                sK[d4 + 3][kk] = vk.w;
                float4 vv = *(const float4*)(Vg + (size_t)(kt * 64 + kk) * stride + d4);
                *(float4*)&sV[kk][d4] = vv;
            }
        }
        __syncthreads();

        float S[4][4];
#pragma unroll
        for (int i = 0; i < 4; i++)
#pragma unroll
            for (int j = 0; j < 4; j++) S[i][j] = 0.f;

#pragma unroll 8
        for (int d = 0; d < 64; d++) {
            float aq[4], bk[4];
            *(float4*)aq = *(const float4*)&sQ[d][ty * 4];
            *(float4*)bk = *(const float4*)&sK[d][tx * 4];
#pragma unroll
            for (int i = 0; i < 4; i++)
#pragma unroll
                for (int j = 0; j < 4; j++)
                    S[i][j] += aq[i] * bk[j];
        }

#pragma unroll
        for (int i = 0; i < 4; i++) {
#pragma unroll
            for (int j = 0; j < 4; j++) S[i][j] *= 0.125f;

            float rm = fmaxf(fmaxf(S[i][0], S[i][1]), fmaxf(S[i][2], S[i][3]));
#pragma unroll
            for (int msk = 1; msk < 16; msk <<= 1)
                rm = fmaxf(rm, __shfl_xor_sync(0xffffffffu, rm, msk));

            const float mn    = fmaxf(m_r[i], rm);
            const float alpha = __expf(m_r[i] - mn);
            m_r[i] = mn;

            float rs = 0.f;
#pragma unroll
            for (int j = 0; j < 4; j++) {
                S[i][j] = __expf(S[i][j] - mn);
                rs += S[i][j];
            }
#pragma unroll
            for (int msk = 1; msk < 16; msk <<= 1)
                rs += __shfl_xor_sync(0xffffffffu, rs, msk);

            l_r[i] = l_r[i] * alpha + rs;
#pragma unroll
            for (int j = 0; j < 4; j++) O[i][j] *= alpha;
        }

#pragma unroll
        for (int i = 0; i < 4; i++)
#pragma unroll
            for (int j = 0; j < 4; j++)
                sP[ty * 4 + i][tx * 4 + j] = S[i][j];
        __syncthreads();

#pragma unroll 8
        for (int kk = 0; kk < 64; kk++) {
            float pf[4], vf[4];
#pragma unroll
            for (int i = 0; i < 4; i++) pf[i] = sP[ty * 4 + i][kk];
            *(float4*)vf = *(const float4*)&sV[kk][tx * 4];
#pragma unroll
            for (int i = 0; i < 4; i++)
#pragma unroll
                for (int j = 0; j < 4; j++)
                    O[i][j] += pf[i] * vf[j];
        }
        __syncthreads();
    }

#pragma unroll
    for (int i = 0; i < 4; i++) {
        const float inv = 1.f / l_r[i];
        const int n = b * L_SEQ + qt * 64 + ty * 4 + i;
        float4 o = make_float4(O[i][0] * inv, O[i][1] * inv,
                               O[i][2] * inv, O[i][3] * inv);
        *(float4*)(ctx + (size_t)n * E_DIM + h * DH + tx * 4) = o;
    }
}

// ---------------------------------------------------------------------------
// Two-stage max over sequence
// ---------------------------------------------------------------------------
__global__ void maxpool_partial(const float* __restrict__ attn, float* __restrict__ part)
{
    const int b = blockIdx.x;
    const int s = blockIdx.y;       // 0..7 -> 64 rows each
    const int e = threadIdx.x;
    const float* p = attn + ((size_t)(b * L_SEQ + s * 64)) * E_DIM + e;
    float m = -INFINITY;
#pragma unroll 8
    for (int l = 0; l < 64; l++)
        m = fmaxf(m, p[(size_t)l * E_DIM]);
    part[((size_t)b * 8 + s) * E_DIM + e] = m;
}

__global__ void maxpool_final(const float* __restrict__ part, float* __restrict__ out)
{
    const int b = blockIdx.x;
    const int e = threadIdx.x;
    const float* p = part + (size_t)b * 8 * E_DIM + e;
    float m = -INFINITY;
#pragma unroll
    for (int s = 0; s < 8; s++)
        m = fmaxf(m, p[(size_t)s * E_DIM]);
    out[b * E_DIM + e] = m;
}

// ---------------------------------------------------------------------------
extern "C" void kernel_launch(void* const* d_in, const int* in_sizes, int n_in,
                              void* d_out, int out_size)
{
    const float* emb   = (const float*)d_in[0];
    // d_in[1] = batch (int32) — equal-size, sorted groups: not needed
    const float* w_in  = (const float*)d_in[2];
    const float* b_in  = (const float*)d_in[3];
    const float* w_out = (const float*)d_in[4];
    const float* b_out = (const float*)d_in[5];
    float* out = (float*)d_out;

    float *qkv_p, *ctx_p, *attn_p, *part_p;
    cudaGetSymbolAddress((void**)&qkv_p,  g_qkv);
    cudaGetSymbolAddress((void**)&ctx_p,  g_ctx);
    cudaGetSymbolAddress((void**)&attn_p, g_attn);
    cudaGetSymbolAddress((void**)&part_p, g_part);

    // 1) QKV projection (TF32 tensor cores): [16384,512] @ [512,1536]^T + b
    dim3 g1((3 * E_DIM) / TBN, N_TOK / TBM);
    sgemm_tf32_bias<<<g1, 256>>>(emb, w_in, b_in, qkv_p, N_TOK, 3 * E_DIM, E_DIM);

    // 2) fused attention: 32 groups x 8 heads x 8 q-tiles
    attn_kernel<<<B_GRP * H_HEADS * 8, 256>>>(qkv_p, ctx_p);

    // 3) out projection (TF32): [16384,512] @ [512,512]^T + b
    dim3 g3(E_DIM / TBN, N_TOK / TBM);
    sgemm_tf32_bias<<<g3, 256>>>(ctx_p, w_out, b_out, attn_p, N_TOK, E_DIM, E_DIM);

    // 4) two-stage max over sequence -> [32, 512]
    maxpool_partial<<<dim3(B_GRP, 8), E_DIM>>>(attn_p, part_p);
    maxpool_final<<<B_GRP, E_DIM>>>(part_p, out);
}

// round 5
// speedup vs baseline: 2.9727x; 1.7649x over previous
#include <cuda_runtime.h>
#include <math.h>
#include <stdint.h>

#define N_TOK   16384
#define E_DIM   512
#define B_GRP   32
#define L_SEQ   512
#define H_HEADS 8
#define DH      64

// Scratch (no allocation allowed -> __device__ globals)
__device__ float g_qkv[N_TOK * 3 * E_DIM];      // [N, 3E]  (Q | K | V)
__device__ float g_ctx[N_TOK * E_DIM];          // [N, E]
__device__ float g_attn[N_TOK * E_DIM];         // [N, E]
__device__ float g_part[B_GRP * 8 * E_DIM];     // maxpool partials

// ---------------------------------------------------------------------------
// TF32 tensor-core helpers
// ---------------------------------------------------------------------------
__device__ __forceinline__ uint32_t f2tf32(float x) {
    uint32_t r;
    asm("cvt.rna.tf32.f32 %0, %1;" : "=r"(r) : "f"(x));
    return r;
}
__device__ __forceinline__ float f2tf32f(float x) {
    return __uint_as_float(f2tf32(x));
}

__device__ __forceinline__ void mma_tf32(float* d, const uint32_t* a,
                                         const uint32_t* b, const float* c) {
    asm volatile(
        "mma.sync.aligned.m16n8k8.row.col.f32.tf32.tf32.f32 "
        "{%0,%1,%2,%3}, {%4,%5,%6,%7}, {%8,%9}, {%10,%11,%12,%13};\n"
        : "=f"(d[0]), "=f"(d[1]), "=f"(d[2]), "=f"(d[3])
        : "r"(a[0]), "r"(a[1]), "r"(a[2]), "r"(a[3]),
          "r"(b[0]), "r"(b[1]),
          "f"(c[0]), "f"(c[1]), "f"(c[2]), "f"(c[3]));
}

// ---------------------------------------------------------------------------
// TF32 SGEMM (NT): C[M,Nn] = A[M,K] @ W[Nn,K]^T + bias  (unchanged from R2)
// ---------------------------------------------------------------------------
#define TBM 128
#define TBN 128
#define TBK 32
#define TPITCH (TBK + 4)

__global__ __launch_bounds__(256, 2) void sgemm_tf32_bias(
    const float* __restrict__ A, const float* __restrict__ W,
    const float* __restrict__ bias, float* __restrict__ C,
    int M, int Nn, int K)
{
    __shared__ __align__(16) float As[TBM][TPITCH];
    __shared__ __align__(16) float Bs[TBN][TPITCH];

    const int tid  = threadIdx.x;
    const int warp = tid >> 5;
    const int lane = tid & 31;
    const int wm   = warp >> 2;
    const int wn   = warp & 3;
    const int g    = lane >> 2;
    const int q    = lane & 3;

    const int brow = blockIdx.y * TBM;
    const int bcol = blockIdx.x * TBN;

    float acc[4][4][4];
#pragma unroll
    for (int mt = 0; mt < 4; mt++)
#pragma unroll
        for (int nt = 0; nt < 4; nt++)
#pragma unroll
            for (int i = 0; i < 4; i++) acc[mt][nt][i] = 0.f;

    const float* Ab = A + (size_t)brow * K;
    const float* Wb = W + (size_t)bcol * K;

    const int lrow = tid >> 3;
    const int lcol = (tid & 7) << 2;

    for (int k0 = 0; k0 < K; k0 += TBK) {
#pragma unroll
        for (int r = 0; r < 4; r++) {
            const int row = lrow + r * 32;
            float4 va = *(const float4*)(Ab + (size_t)row * K + k0 + lcol);
            float4 ta;
            ta.x = f2tf32f(va.x); ta.y = f2tf32f(va.y);
            ta.z = f2tf32f(va.z); ta.w = f2tf32f(va.w);
            *(float4*)&As[row][lcol] = ta;

            float4 vb = *(const float4*)(Wb + (size_t)row * K + k0 + lcol);
            float4 tb;
            tb.x = f2tf32f(vb.x); tb.y = f2tf32f(vb.y);
            tb.z = f2tf32f(vb.z); tb.w = f2tf32f(vb.w);
            *(float4*)&Bs[row][lcol] = tb;
        }
        __syncthreads();

#pragma unroll
        for (int ks = 0; ks < 4; ks++) {
            const int k = ks * 8;
            uint32_t af[4][4];
            uint32_t bf[4][2];
#pragma unroll
            for (int mt = 0; mt < 4; mt++) {
                const int r0 = wm * 64 + mt * 16 + g;
                af[mt][0] = __float_as_uint(As[r0][k + q]);
                af[mt][1] = __float_as_uint(As[r0 + 8][k + q]);
                af[mt][2] = __float_as_uint(As[r0][k + 4 + q]);
                af[mt][3] = __float_as_uint(As[r0 + 8][k + 4 + q]);
            }
#pragma unroll
            for (int nt = 0; nt < 4; nt++) {
                const int c0 = wn * 32 + nt * 8 + g;
                bf[nt][0] = __float_as_uint(Bs[c0][k + q]);
                bf[nt][1] = __float_as_uint(Bs[c0][k + 4 + q]);
            }
#pragma unroll
            for (int mt = 0; mt < 4; mt++)
#pragma unroll
                for (int nt = 0; nt < 4; nt++)
                    mma_tf32(acc[mt][nt], af[mt], bf[nt], acc[mt][nt]);
        }
        __syncthreads();
    }

#pragma unroll
    for (int nt = 0; nt < 4; nt++) {
        const int col = bcol + wn * 32 + nt * 8 + 2 * q;
        const float b0 = bias[col];
        const float b1 = bias[col + 1];
#pragma unroll
        for (int mt = 0; mt < 4; mt++) {
            const int r0 = brow + wm * 64 + mt * 16 + g;
            float2 v0 = make_float2(acc[mt][nt][0] + b0, acc[mt][nt][1] + b1);
            float2 v1 = make_float2(acc[mt][nt][2] + b0, acc[mt][nt][3] + b1);
            *(float2*)(C + (size_t)r0 * Nn + col)       = v0;
            *(float2*)(C + (size_t)(r0 + 8) * Nn + col) = v1;
        }
    }
}

// ---------------------------------------------------------------------------
// TF32 tensor-core flash attention.
// CTA = (b, h, 64-row q tile). 128 threads = 4 warps, each owns 16 q rows.
// S = Q@K^T and O += P@V both via m16n8k8 row.col MMA.
//   - K tile [k][d] is directly the B operand for S (row.col => implicit K^T)
//   - V tile [k][d] is directly the B operand for PV (implicit V^T of V^T)
// P round-trips through smem reusing the K buffer (union).
// ---------------------------------------------------------------------------
#define KP_PITCH 68   // K/P/Q staging: frag reads conflict-free (bank=4g+q+c)
#define V_PITCH  72   // V: B-frag reads conflict-free (bank=8q+g+c)

__global__ __launch_bounds__(128, 2) void attn_tf32(
    const float* __restrict__ qkv, float* __restrict__ ctx)
{
    __shared__ __align__(16) float sKP[64][KP_PITCH];  // K tile / P tile / Q stage
    __shared__ __align__(16) float sV[64][V_PITCH];    // V tile [k][d]

    const int tid  = threadIdx.x;
    const int warp = tid >> 5;
    const int lane = tid & 31;
    const int g    = lane >> 2;   // 0..7
    const int q    = lane & 3;    // 0..3

    const int qt  = blockIdx.x & 7;
    const int bh  = blockIdx.x >> 3;
    const int h   = bh & 7;
    const int b   = bh >> 3;

    const size_t stride = 3 * E_DIM;
    const float* Qg = qkv + (size_t)(b * L_SEQ + qt * 64) * stride + h * DH;
    const float* Kg = qkv + (size_t)(b * L_SEQ) * stride + E_DIM + h * DH;
    const float* Vg = qkv + (size_t)(b * L_SEQ) * stride + 2 * E_DIM + h * DH;

    const int ldr = tid >> 4;          // 0..7
    const int ldc = (tid & 15) << 2;   // 0..60 step 4

    // ---- stage Q (tf32) -> pull A-frags into registers (kept all kernel) ----
#pragma unroll
    for (int rr = 0; rr < 64; rr += 8) {
        const int row = rr + ldr;
        float4 v = *(const float4*)(Qg + (size_t)row * stride + ldc);
        float4 t;
        t.x = f2tf32f(v.x); t.y = f2tf32f(v.y);
        t.z = f2tf32f(v.z); t.w = f2tf32f(v.w);
        *(float4*)&sKP[row][ldc] = t;
    }
    __syncthreads();

    const int qrow = warp * 16 + g;
    uint32_t Qf[8][4];
#pragma unroll
    for (int ks = 0; ks < 8; ks++) {
        const int k = ks * 8;
        Qf[ks][0] = __float_as_uint(sKP[qrow][k + q]);
        Qf[ks][1] = __float_as_uint(sKP[qrow + 8][k + q]);
        Qf[ks][2] = __float_as_uint(sKP[qrow][k + 4 + q]);
        Qf[ks][3] = __float_as_uint(sKP[qrow + 8][k + 4 + q]);
    }
    __syncthreads();

    float O[8][4];
#pragma unroll
    for (int nt = 0; nt < 8; nt++)
#pragma unroll
        for (int i = 0; i < 4; i++) O[nt][i] = 0.f;
    float m0 = -INFINITY, m1 = -INFINITY, l0 = 0.f, l1 = 0.f;

    for (int kt = 0; kt < 8; kt++) {
        // ---- load K tile and V tile (coalesced, tf32-converted) ----
#pragma unroll
        for (int rr = 0; rr < 64; rr += 8) {
            const int row = rr + ldr;
            float4 vk = *(const float4*)(Kg + (size_t)(kt * 64 + row) * stride + ldc);
            float4 tk;
            tk.x = f2tf32f(vk.x); tk.y = f2tf32f(vk.y);
            tk.z = f2tf32f(vk.z); tk.w = f2tf32f(vk.w);
            *(float4*)&sKP[row][ldc] = tk;

            float4 vv = *(const float4*)(Vg + (size_t)(kt * 64 + row) * stride + ldc);
            float4 tv;
            tv.x = f2tf32f(vv.x); tv.y = f2tf32f(vv.y);
            tv.z = f2tf32f(vv.z); tv.w = f2tf32f(vv.w);
            *(float4*)&sV[row][ldc] = tv;
        }
        __syncthreads();

        // ---- S = Q @ K^T : B-frag = sKP[key][d] directly ----
        float S[8][4];
#pragma unroll
        for (int nt = 0; nt < 8; nt++)
#pragma unroll
            for (int i = 0; i < 4; i++) S[nt][i] = 0.f;

#pragma unroll
        for (int ks = 0; ks < 8; ks++) {
            const int k = ks * 8;
            uint32_t bf[8][2];
#pragma unroll
            for (int nt = 0; nt < 8; nt++) {
                bf[nt][0] = __float_as_uint(sKP[nt * 8 + g][k + q]);
                bf[nt][1] = __float_as_uint(sKP[nt * 8 + g][k + 4 + q]);
            }
#pragma unroll
            for (int nt = 0; nt < 8; nt++)
                mma_tf32(S[nt], Qf[ks], bf[nt], S[nt]);
        }

        // ---- online softmax (rows g / g+8; reduce over q-lanes) ----
        float rm0 = -INFINITY, rm1 = -INFINITY;
#pragma unroll
        for (int nt = 0; nt < 8; nt++) {
            S[nt][0] *= 0.125f; S[nt][1] *= 0.125f;
            S[nt][2] *= 0.125f; S[nt][3] *= 0.125f;
            rm0 = fmaxf(rm0, fmaxf(S[nt][0], S[nt][1]));
            rm1 = fmaxf(rm1, fmaxf(S[nt][2], S[nt][3]));
        }
        rm0 = fmaxf(rm0, __shfl_xor_sync(0xffffffffu, rm0, 1));
        rm0 = fmaxf(rm0, __shfl_xor_sync(0xffffffffu, rm0, 2));
        rm1 = fmaxf(rm1, __shfl_xor_sync(0xffffffffu, rm1, 1));
        rm1 = fmaxf(rm1, __shfl_xor_sync(0xffffffffu, rm1, 2));

        const float mn0 = fmaxf(m0, rm0);
        const float mn1 = fmaxf(m1, rm1);
        const float a0 = __expf(m0 - mn0);
        const float a1 = __expf(m1 - mn1);
        m0 = mn0; m1 = mn1;

        float rs0 = 0.f, rs1 = 0.f;
#pragma unroll
        for (int nt = 0; nt < 8; nt++) {
            S[nt][0] = __expf(S[nt][0] - mn0);
            S[nt][1] = __expf(S[nt][1] - mn0);
            S[nt][2] = __expf(S[nt][2] - mn1);
            S[nt][3] = __expf(S[nt][3] - mn1);
            rs0 += S[nt][0] + S[nt][1];
            rs1 += S[nt][2] + S[nt][3];
        }
        rs0 += __shfl_xor_sync(0xffffffffu, rs0, 1);
        rs0 += __shfl_xor_sync(0xffffffffu, rs0, 2);
        rs1 += __shfl_xor_sync(0xffffffffu, rs1, 1);
        rs1 += __shfl_xor_sync(0xffffffffu, rs1, 2);

        l0 = l0 * a0 + rs0;
        l1 = l1 * a1 + rs1;
#pragma unroll
        for (int nt = 0; nt < 8; nt++) {
            O[nt][0] *= a0; O[nt][1] *= a0;
            O[nt][2] *= a1; O[nt][3] *= a1;
        }

        __syncthreads();   // everyone done reading K from sKP

        // ---- write P (tf32) into sKP ----
#pragma unroll
        for (int nt = 0; nt < 8; nt++) {
            const int c = nt * 8 + 2 * q;
            sKP[qrow][c]         = f2tf32f(S[nt][0]);
            sKP[qrow][c + 1]     = f2tf32f(S[nt][1]);
            sKP[qrow + 8][c]     = f2tf32f(S[nt][2]);
            sKP[qrow + 8][c + 1] = f2tf32f(S[nt][3]);
        }
        __syncthreads();

        // ---- O += P @ V : A-frag from sKP (P), B-frag = sV[key][d] ----
#pragma unroll
        for (int ks = 0; ks < 8; ks++) {
            const int k = ks * 8;
            uint32_t af[4];
            af[0] = __float_as_uint(sKP[qrow][k + q]);
            af[1] = __float_as_uint(sKP[qrow + 8][k + q]);
            af[2] = __float_as_uint(sKP[qrow][k + 4 + q]);
            af[3] = __float_as_uint(sKP[qrow + 8][k + 4 + q]);
#pragma unroll
            for (int nt = 0; nt < 8; nt++) {
                uint32_t bf[2];
                bf[0] = __float_as_uint(sV[k + q][nt * 8 + g]);
                bf[1] = __float_as_uint(sV[k + 4 + q][nt * 8 + g]);
                mma_tf32(O[nt], af, bf, O[nt]);
            }
        }
        __syncthreads();   // before next kt overwrites sKP / sV
    }

    // ---- normalize + store ctx ----
    const float inv0 = 1.f / l0;
    const float inv1 = 1.f / l1;
    const int row0 = b * L_SEQ + qt * 64 + qrow;
#pragma unroll
    for (int nt = 0; nt < 8; nt++) {
        const int c = h * DH + nt * 8 + 2 * q;
        *(float2*)(ctx + (size_t)row0 * E_DIM + c) =
            make_float2(O[nt][0] * inv0, O[nt][1] * inv0);
        *(float2*)(ctx + (size_t)(row0 + 8) * E_DIM + c) =
            make_float2(O[nt][2] * inv1, O[nt][3] * inv1);
    }
}

// ---------------------------------------------------------------------------
// Two-stage max over sequence
// ---------------------------------------------------------------------------
__global__ void maxpool_partial(const float* __restrict__ attn, float* __restrict__ part)
{
    const int b = blockIdx.x;
    const int s = blockIdx.y;
    const int e = threadIdx.x;
    const float* p = attn + ((size_t)(b * L_SEQ + s * 64)) * E_DIM + e;
    float m = -INFINITY;
#pragma unroll 8
    for (int l = 0; l < 64; l++)
        m = fmaxf(m, p[(size_t)l * E_DIM]);
    part[((size_t)b * 8 + s) * E_DIM + e] = m;
}

__global__ void maxpool_final(const float* __restrict__ part, float* __restrict__ out)
{
    const int b = blockIdx.x;
    const int e = threadIdx.x;
    const float* p = part + (size_t)b * 8 * E_DIM + e;
    float m = -INFINITY;
#pragma unroll
    for (int s = 0; s < 8; s++)
        m = fmaxf(m, p[(size_t)s * E_DIM]);
    out[b * E_DIM + e] = m;
}

// ---------------------------------------------------------------------------
extern "C" void kernel_launch(void* const* d_in, const int* in_sizes, int n_in,
                              void* d_out, int out_size)
{
    const float* emb   = (const float*)d_in[0];
    // d_in[1] = batch (int32) — equal-size, sorted groups: not needed
    const float* w_in  = (const float*)d_in[2];
    const float* b_in  = (const float*)d_in[3];
    const float* w_out = (const float*)d_in[4];
    const float* b_out = (const float*)d_in[5];
    float* out = (float*)d_out;

    float *qkv_p, *ctx_p, *attn_p, *part_p;
    cudaGetSymbolAddress((void**)&qkv_p,  g_qkv);
    cudaGetSymbolAddress((void**)&ctx_p,  g_ctx);
    cudaGetSymbolAddress((void**)&attn_p, g_attn);
    cudaGetSymbolAddress((void**)&part_p, g_part);

    // 1) QKV projection (TF32): [16384,512] @ [512,1536]^T + b
    dim3 g1((3 * E_DIM) / TBN, N_TOK / TBM);
    sgemm_tf32_bias<<<g1, 256>>>(emb, w_in, b_in, qkv_p, N_TOK, 3 * E_DIM, E_DIM);

    // 2) TF32 tensor-core flash attention: 32 groups x 8 heads x 8 q-tiles
    attn_tf32<<<B_GRP * H_HEADS * 8, 128>>>(qkv_p, ctx_p);

    // 3) out projection (TF32): [16384,512] @ [512,512]^T + b
    dim3 g3(E_DIM / TBN, N_TOK / TBM);
    sgemm_tf32_bias<<<g3, 256>>>(ctx_p, w_out, b_out, attn_p, N_TOK, E_DIM, E_DIM);

    // 4) two-stage max over sequence -> [32, 512]
    maxpool_partial<<<dim3(B_GRP, 8), E_DIM>>>(attn_p, part_p);
    maxpool_final<<<B_GRP, E_DIM>>>(part_p, out);
}

// round 9
// speedup vs baseline: 3.1394x; 1.0561x over previous
#include <cuda_runtime.h>
#include <math.h>
#include <stdint.h>

#define N_TOK   16384
#define E_DIM   512
#define B_GRP   32
#define L_SEQ   512
#define H_HEADS 8
#define DH      64

// Scratch (no allocation allowed -> __device__ globals)
__device__ float g_qkv[N_TOK * 3 * E_DIM];      // [N, 3E]  (Q | K | V)
__device__ float g_ctx[N_TOK * E_DIM];          // [N, E]
__device__ float g_part[(N_TOK / 128) * E_DIM]; // fused-max partials [128][512]

// ---------------------------------------------------------------------------
// TF32 tensor-core helpers (legacy mma path — tcgen05 not available: the
// harness PTX target is sm_103 without the 'a' feature set)
// ---------------------------------------------------------------------------
__device__ __forceinline__ uint32_t f2tf32(float x) {
    uint32_t r;
    asm("cvt.rna.tf32.f32 %0, %1;" : "=r"(r) : "f"(x));
    return r;
}
__device__ __forceinline__ float f2tf32f(float x) {
    return __uint_as_float(f2tf32(x));
}

__device__ __forceinline__ void mma_tf32(float* d, const uint32_t* a,
                                         const uint32_t* b, const float* c) {
    asm volatile(
        "mma.sync.aligned.m16n8k8.row.col.f32.tf32.tf32.f32 "
        "{%0,%1,%2,%3}, {%4,%5,%6,%7}, {%8,%9}, {%10,%11,%12,%13};\n"
        : "=f"(d[0]), "=f"(d[1]), "=f"(d[2]), "=f"(d[3])
        : "r"(a[0]), "r"(a[1]), "r"(a[2]), "r"(a[3]),
          "r"(b[0]), "r"(b[1]),
          "f"(c[0]), "f"(c[1]), "f"(c[2]), "f"(c[3]));
}

// ---------------------------------------------------------------------------
// TF32 GEMM (NT): C[M,Nn] = A[M,K] @ W[Nn,K]^T + bias
// 128x128 CTA tile, BK=32, 256 threads (8 warps, 2x4), warp tile 64x32.
// Register-prefetch pipelined: t+1 global loads issued before compute(t).
// WRITE_C: store C.  DO_MAX: skip C store, emit per-CTA column max + bias
// into part[blockIdx.y * Nn + col] (for the fused maxpool).
// ---------------------------------------------------------------------------
#define TBM 128
#define TBN 128
#define TBK 32
#define TPITCH (TBK + 4)

template <bool WRITE_C, bool DO_MAX>
__global__ __launch_bounds__(256, 2) void sgemm_tf32(
    const float* __restrict__ A, const float* __restrict__ W,
    const float* __restrict__ bias, float* __restrict__ C,
    float* __restrict__ part, int M, int Nn, int K)
{
    __shared__ __align__(16) float As[TBM][TPITCH];
    __shared__ __align__(16) float Bs[TBN][TPITCH];
    __shared__ float smax[TBN];

    const int tid  = threadIdx.x;
    const int warp = tid >> 5;
    const int lane = tid & 31;
    const int wm   = warp >> 2;
    const int wn   = warp & 3;
    const int g    = lane >> 2;
    const int q    = lane & 3;

    const int brow = blockIdx.y * TBM;
    const int bcol = blockIdx.x * TBN;

    float acc[4][4][4];
#pragma unroll
    for (int mt = 0; mt < 4; mt++)
#pragma unroll
        for (int nt = 0; nt < 4; nt++)
#pragma unroll
            for (int i = 0; i < 4; i++) acc[mt][nt][i] = 0.f;

    const float* Ab = A + (size_t)brow * K;
    const float* Wb = W + (size_t)bcol * K;

    const int lrow = tid >> 3;        // 0..31
    const int lcol = (tid & 7) << 2;  // 0..28 step 4
    const int NT = K / TBK;

    float4 pa[4], pb[4];

    // prologue: load + stage tile 0
#pragma unroll
    for (int r = 0; r < 4; r++) {
        const int row = lrow + r * 32;
        pa[r] = *(const float4*)(Ab + (size_t)row * K + lcol);
        pb[r] = *(const float4*)(Wb + (size_t)row * K + lcol);
    }
#pragma unroll
    for (int r = 0; r < 4; r++) {
        const int row = lrow + r * 32;
        float4 ta, tb;
        ta.x = f2tf32f(pa[r].x); ta.y = f2tf32f(pa[r].y);
        ta.z = f2tf32f(pa[r].z); ta.w = f2tf32f(pa[r].w);
        *(float4*)&As[row][lcol] = ta;
        tb.x = f2tf32f(pb[r].x); tb.y = f2tf32f(pb[r].y);
        tb.z = f2tf32f(pb[r].z); tb.w = f2tf32f(pb[r].w);
        *(float4*)&Bs[row][lcol] = tb;
    }
    __syncthreads();

    for (int t = 0; t < NT; t++) {
        // prefetch t+1 (global -> regs), hidden under the MMA phase
        if (t + 1 < NT) {
            const int kb = (t + 1) * TBK;
#pragma unroll
            for (int r = 0; r < 4; r++) {
                const int row = lrow + r * 32;
                pa[r] = *(const float4*)(Ab + (size_t)row * K + kb + lcol);
                pb[r] = *(const float4*)(Wb + (size_t)row * K + kb + lcol);
            }
        }

        // compute on staged tile
#pragma unroll
        for (int ks = 0; ks < 4; ks++) {
            const int k = ks * 8;
            uint32_t af[4][4];
            uint32_t bf[4][2];
#pragma unroll
            for (int mt = 0; mt < 4; mt++) {
                const int r0 = wm * 64 + mt * 16 + g;
                af[mt][0] = __float_as_uint(As[r0][k + q]);
                af[mt][1] = __float_as_uint(As[r0 + 8][k + q]);
                af[mt][2] = __float_as_uint(As[r0][k + 4 + q]);
                af[mt][3] = __float_as_uint(As[r0 + 8][k + 4 + q]);
            }
#pragma unroll
            for (int nt = 0; nt < 4; nt++) {
                const int c0 = wn * 32 + nt * 8 + g;
                bf[nt][0] = __float_as_uint(Bs[c0][k + q]);
                bf[nt][1] = __float_as_uint(Bs[c0][k + 4 + q]);
            }
#pragma unroll
            for (int mt = 0; mt < 4; mt++)
#pragma unroll
                for (int nt = 0; nt < 4; nt++)
                    mma_tf32(acc[mt][nt], af[mt], bf[nt], acc[mt][nt]);
        }
        __syncthreads();

        if (t + 1 < NT) {
#pragma unroll
            for (int r = 0; r < 4; r++) {
                const int row = lrow + r * 32;
                float4 ta, tb;
                ta.x = f2tf32f(pa[r].x); ta.y = f2tf32f(pa[r].y);
                ta.z = f2tf32f(pa[r].z); ta.w = f2tf32f(pa[r].w);
                *(float4*)&As[row][lcol] = ta;
                tb.x = f2tf32f(pb[r].x); tb.y = f2tf32f(pb[r].y);
                tb.z = f2tf32f(pb[r].z); tb.w = f2tf32f(pb[r].w);
                *(float4*)&Bs[row][lcol] = tb;
            }
            __syncthreads();
        }
    }

    if (WRITE_C) {
#pragma unroll
        for (int nt = 0; nt < 4; nt++) {
            const int col = bcol + wn * 32 + nt * 8 + 2 * q;
            const float b0 = bias[col];
            const float b1 = bias[col + 1];
#pragma unroll
            for (int mt = 0; mt < 4; mt++) {
                const int r0 = brow + wm * 64 + mt * 16 + g;
                float2 v0 = make_float2(acc[mt][nt][0] + b0, acc[mt][nt][1] + b1);
                float2 v1 = make_float2(acc[mt][nt][2] + b0, acc[mt][nt][3] + b1);
                *(float2*)(C + (size_t)r0 * Nn + col)       = v0;
                *(float2*)(C + (size_t)(r0 + 8) * Nn + col) = v1;
            }
        }
    }

    if (DO_MAX) {
        // per-thread column max over its 16 rows (bias added after max)
        float cm[4][2];
#pragma unroll
        for (int nt = 0; nt < 4; nt++) {
            float m0 = -INFINITY, m1 = -INFINITY;
#pragma unroll
            for (int mt = 0; mt < 4; mt++) {
                m0 = fmaxf(m0, fmaxf(acc[mt][nt][0], acc[mt][nt][2]));
                m1 = fmaxf(m1, fmaxf(acc[mt][nt][1], acc[mt][nt][3]));
            }
            cm[nt][0] = m0; cm[nt][1] = m1;
        }
        // reduce over the 8 g-lanes (same columns, different rows)
#pragma unroll
        for (int nt = 0; nt < 4; nt++)
#pragma unroll
            for (int jj = 0; jj < 2; jj++) {
                float v = cm[nt][jj];
                v = fmaxf(v, __shfl_xor_sync(0xffffffffu, v, 4));
                v = fmaxf(v, __shfl_xor_sync(0xffffffffu, v, 8));
                v = fmaxf(v, __shfl_xor_sync(0xffffffffu, v, 16));
                cm[nt][jj] = v;
            }
        // cross-warp merge (wm=0 writes, wm=1 maxes)
        if (wm == 0 && g == 0) {
#pragma unroll
            for (int nt = 0; nt < 4; nt++) {
                smax[wn * 32 + nt * 8 + 2 * q]     = cm[nt][0];
                smax[wn * 32 + nt * 8 + 2 * q + 1] = cm[nt][1];
            }
        }
        __syncthreads();
        if (wm == 1 && g == 0) {
#pragma unroll
            for (int nt = 0; nt < 4; nt++) {
                const int c = wn * 32 + nt * 8 + 2 * q;
                smax[c]     = fmaxf(smax[c],     cm[nt][0]);
                smax[c + 1] = fmaxf(smax[c + 1], cm[nt][1]);
            }
        }
        __syncthreads();
        if (tid < TBN) {
            const int col = bcol + tid;
            part[(size_t)blockIdx.y * Nn + col] = smax[tid] + bias[col];
        }
    }
}

// ---------------------------------------------------------------------------
// TF32 tensor-core flash attention (R5 best, unchanged)
// ---------------------------------------------------------------------------
#define KP_PITCH 68
#define V_PITCH  72

__global__ __launch_bounds__(128, 2) void attn_tf32(
    const float* __restrict__ qkv, float* __restrict__ ctx)
{
    __shared__ __align__(16) float sKP[64][KP_PITCH];
    __shared__ __align__(16) float sV[64][V_PITCH];

    const int tid  = threadIdx.x;
    const int warp = tid >> 5;
    const int lane = tid & 31;
    const int g    = lane >> 2;
    const int q    = lane & 3;

    const int qt  = blockIdx.x & 7;
    const int bh  = blockIdx.x >> 3;
    const int h   = bh & 7;
    const int b   = bh >> 3;

    const size_t stride = 3 * E_DIM;
    const float* Qg = qkv + (size_t)(b * L_SEQ + qt * 64) * stride + h * DH;
    const float* Kg = qkv + (size_t)(b * L_SEQ) * stride + E_DIM + h * DH;
    const float* Vg = qkv + (size_t)(b * L_SEQ) * stride + 2 * E_DIM + h * DH;

    const int ldr = tid >> 4;
    const int ldc = (tid & 15) << 2;

#pragma unroll
    for (int rr = 0; rr < 64; rr += 8) {
        const int row = rr + ldr;
        float4 v = *(const float4*)(Qg + (size_t)row * stride + ldc);
        float4 t;
        t.x = f2tf32f(v.x); t.y = f2tf32f(v.y);
        t.z = f2tf32f(v.z); t.w = f2tf32f(v.w);
        *(float4*)&sKP[row][ldc] = t;
    }
    __syncthreads();

    const int qrow = warp * 16 + g;
    uint32_t Qf[8][4];
#pragma unroll
    for (int ks = 0; ks < 8; ks++) {
        const int k = ks * 8;
        Qf[ks][0] = __float_as_uint(sKP[qrow][k + q]);
        Qf[ks][1] = __float_as_uint(sKP[qrow + 8][k + q]);
        Qf[ks][2] = __float_as_uint(sKP[qrow][k + 4 + q]);
        Qf[ks][3] = __float_as_uint(sKP[qrow + 8][k + 4 + q]);
    }
    __syncthreads();

    float O[8][4];
#pragma unroll
    for (int nt = 0; nt < 8; nt++)
#pragma unroll
        for (int i = 0; i < 4; i++) O[nt][i] = 0.f;
    float m0 = -INFINITY, m1 = -INFINITY, l0 = 0.f, l1 = 0.f;

    for (int kt = 0; kt < 8; kt++) {
#pragma unroll
        for (int rr = 0; rr < 64; rr += 8) {
            const int row = rr + ldr;
            float4 vk = *(const float4*)(Kg + (size_t)(kt * 64 + row) * stride + ldc);
            float4 tk;
            tk.x = f2tf32f(vk.x); tk.y = f2tf32f(vk.y);
            tk.z = f2tf32f(vk.z); tk.w = f2tf32f(vk.w);
            *(float4*)&sKP[row][ldc] = tk;

            float4 vv = *(const float4*)(Vg + (size_t)(kt * 64 + row) * stride + ldc);
            float4 tv;
            tv.x = f2tf32f(vv.x); tv.y = f2tf32f(vv.y);
            tv.z = f2tf32f(vv.z); tv.w = f2tf32f(vv.w);
            *(float4*)&sV[row][ldc] = tv;
        }
        __syncthreads();

        float S[8][4];
#pragma unroll
        for (int nt = 0; nt < 8; nt++)
#pragma unroll
            for (int i = 0; i < 4; i++) S[nt][i] = 0.f;

#pragma unroll
        for (int ks = 0; ks < 8; ks++) {
            const int k = ks * 8;
            uint32_t bf[8][2];
#pragma unroll
            for (int nt = 0; nt < 8; nt++) {
                bf[nt][0] = __float_as_uint(sKP[nt * 8 + g][k + q]);
                bf[nt][1] = __float_as_uint(sKP[nt * 8 + g][k + 4 + q]);
            }
#pragma unroll
            for (int nt = 0; nt < 8; nt++)
                mma_tf32(S[nt], Qf[ks], bf[nt], S[nt]);
        }

        float rm0 = -INFINITY, rm1 = -INFINITY;
#pragma unroll
        for (int nt = 0; nt < 8; nt++) {
            S[nt][0] *= 0.125f; S[nt][1] *= 0.125f;
            S[nt][2] *= 0.125f; S[nt][3] *= 0.125f;
            rm0 = fmaxf(rm0, fmaxf(S[nt][0], S[nt][1]));
            rm1 = fmaxf(rm1, fmaxf(S[nt][2], S[nt][3]));
        }
        rm0 = fmaxf(rm0, __shfl_xor_sync(0xffffffffu, rm0, 1));
        rm0 = fmaxf(rm0, __shfl_xor_sync(0xffffffffu, rm0, 2));
        rm1 = fmaxf(rm1, __shfl_xor_sync(0xffffffffu, rm1, 1));
        rm1 = fmaxf(rm1, __shfl_xor_sync(0xffffffffu, rm1, 2));

        const float mn0 = fmaxf(m0, rm0);
        const float mn1 = fmaxf(m1, rm1);
        const float a0 = __expf(m0 - mn0);
        const float a1 = __expf(m1 - mn1);
        m0 = mn0; m1 = mn1;

        float rs0 = 0.f, rs1 = 0.f;
#pragma unroll
        for (int nt = 0; nt < 8; nt++) {
            S[nt][0] = __expf(S[nt][0] - mn0);
            S[nt][1] = __expf(S[nt][1] - mn0);
            S[nt][2] = __expf(S[nt][2] - mn1);
            S[nt][3] = __expf(S[nt][3] - mn1);
            rs0 += S[nt][0] + S[nt][1];
            rs1 += S[nt][2] + S[nt][3];
        }
        rs0 += __shfl_xor_sync(0xffffffffu, rs0, 1);
        rs0 += __shfl_xor_sync(0xffffffffu, rs0, 2);
        rs1 += __shfl_xor_sync(0xffffffffu, rs1, 1);
        rs1 += __shfl_xor_sync(0xffffffffu, rs1, 2);

        l0 = l0 * a0 + rs0;
        l1 = l1 * a1 + rs1;
#pragma unroll
        for (int nt = 0; nt < 8; nt++) {
            O[nt][0] *= a0; O[nt][1] *= a0;
            O[nt][2] *= a1; O[nt][3] *= a1;
        }

        __syncthreads();

#pragma unroll
        for (int nt = 0; nt < 8; nt++) {
            const int c = nt * 8 + 2 * q;
            sKP[qrow][c]         = f2tf32f(S[nt][0]);
            sKP[qrow][c + 1]     = f2tf32f(S[nt][1]);
            sKP[qrow + 8][c]     = f2tf32f(S[nt][2]);
            sKP[qrow + 8][c + 1] = f2tf32f(S[nt][3]);
        }
        __syncthreads();

#pragma unroll
        for (int ks = 0; ks < 8; ks++) {
            const int k = ks * 8;
            uint32_t af[4];
            af[0] = __float_as_uint(sKP[qrow][k + q]);
            af[1] = __float_as_uint(sKP[qrow + 8][k + q]);
            af[2] = __float_as_uint(sKP[qrow][k + 4 + q]);
            af[3] = __float_as_uint(sKP[qrow + 8][k + 4 + q]);
#pragma unroll
            for (int nt = 0; nt < 8; nt++) {
                uint32_t bf[2];
                bf[0] = __float_as_uint(sV[k + q][nt * 8 + g]);
                bf[1] = __float_as_uint(sV[k + 4 + q][nt * 8 + g]);
                mma_tf32(O[nt], af, bf, O[nt]);
            }
        }
        __syncthreads();
    }

    const float inv0 = 1.f / l0;
    const float inv1 = 1.f / l1;
    const int row0 = b * L_SEQ + qt * 64 + qrow;
#pragma unroll
    for (int nt = 0; nt < 8; nt++) {
        const int c = h * DH + nt * 8 + 2 * q;
        *(float2*)(ctx + (size_t)row0 * E_DIM + c) =
            make_float2(O[nt][0] * inv0, O[nt][1] * inv0);
        *(float2*)(ctx + (size_t)(row0 + 8) * E_DIM + c) =
            make_float2(O[nt][2] * inv1, O[nt][3] * inv1);
    }
}

// ---------------------------------------------------------------------------
// Final max: out[b][e] = max over 4 row-blocks of part[(4b+rb)*E + e]
// ---------------------------------------------------------------------------
__global__ void maxpool_final(const float* __restrict__ part, float* __restrict__ out)
{
    const int b = blockIdx.x;
    const int e = threadIdx.x;
    const float* p = part + (size_t)(b * 4) * E_DIM + e;
    float m = p[0];
#pragma unroll
    for (int s = 1; s < 4; s++)
        m = fmaxf(m, p[(size_t)s * E_DIM]);
    out[b * E_DIM + e] = m;
}

// ---------------------------------------------------------------------------
extern "C" void kernel_launch(void* const* d_in, const int* in_sizes, int n_in,
                              void* d_out, int out_size)
{
    const float* emb   = (const float*)d_in[0];
    // d_in[1] = batch (int32) — equal-size, sorted groups: not needed
    const float* w_in  = (const float*)d_in[2];
    const float* b_in  = (const float*)d_in[3];
    const float* w_out = (const float*)d_in[4];
    const float* b_out = (const float*)d_in[5];
    float* out = (float*)d_out;

    float *qkv_p, *ctx_p, *part_p;
    cudaGetSymbolAddress((void**)&qkv_p,  g_qkv);
    cudaGetSymbolAddress((void**)&ctx_p,  g_ctx);
    cudaGetSymbolAddress((void**)&part_p, g_part);

    // 1) QKV projection (TF32 mma, pipelined): [16384,512] @ [512,1536]^T + b
    dim3 g1((3 * E_DIM) / TBN, N_TOK / TBM);
    sgemm_tf32<true, false><<<g1, 256>>>(emb, w_in, b_in, qkv_p, nullptr,
                                         N_TOK, 3 * E_DIM, E_DIM);

    // 2) TF32 tensor-core flash attention
    attn_tf32<<<B_GRP * H_HEADS * 8, 128>>>(qkv_p, ctx_p);

    // 3) out projection fused with column-max epilogue (no attn matrix store)
    dim3 g3(E_DIM / TBN, N_TOK / TBM);
    sgemm_tf32<false, true><<<g3, 256>>>(ctx_p, w_out, b_out, nullptr, part_p,
                                         N_TOK, E_DIM, E_DIM);

    // 4) final max over the 4 row-blocks per group -> [32, 512]
    maxpool_final<<<B_GRP, E_DIM>>>(part_p, out);
}